// round 3
// baseline (speedup 1.0000x reference)
#include <cuda_runtime.h>
#include <math.h>
#include <stdint.h>

#define N_NODESC 50000
#define N_EDGESC 800000
#define CCH      128
#define N_GRAPHS 512
#define N_OUTC   5

// ---------------- scratch (device globals: allocation-free) ----------------
__device__ __align__(128) float g_h [N_NODESC * CCH];   // h = x + aggr
__device__ __align__(128) float g_h1[N_NODESC * CCH];   // after first linear
__device__ __align__(128) float g_xo[N_NODESC * CCH];   // layer output
__device__ __align__(128) float g_stats [2 * CCH];      // col sums / sumsq
__device__ __align__(128) float g_affine[2 * CCH];      // BN scale / shift
__device__ __align__(128) float g_pool[N_GRAPHS * CCH]; // max pool

// ---------------- packed f32x2 helpers (FFMA2) ------------------------------
__device__ __forceinline__ unsigned long long fma2(unsigned long long a,
                                                   unsigned long long b,
                                                   unsigned long long c) {
    unsigned long long d;
    asm("fma.rn.f32x2 %0, %1, %2, %3;" : "=l"(d) : "l"(a), "l"(b), "l"(c));
    return d;
}
__device__ __forceinline__ unsigned long long pack2(float x, float y) {
    unsigned long long d;
    asm("mov.b64 %0, {%1, %2};" : "=l"(d)
        : "r"(__float_as_uint(x)), "r"(__float_as_uint(y)));
    return d;
}
__device__ __forceinline__ float lo2(unsigned long long v) {
    return __uint_as_float((unsigned)v);
}
__device__ __forceinline__ float hi2(unsigned long long v) {
    return __uint_as_float((unsigned)(v >> 32));
}

// ---------------- helpers ----------------
__global__ void copy4_kernel(float4* __restrict__ dst, const float4* __restrict__ src, int n) {
    int i = blockIdx.x * blockDim.x + threadIdx.x;
    if (i < n) dst[i] = src[i];
}

__global__ void zero_stats_kernel() {
    g_stats[threadIdx.x] = 0.f;          // 256 threads cover 2*CCH
}

__global__ void zero_pool_kernel() {
    int i = blockIdx.x * blockDim.x + threadIdx.x;
    if (i < N_GRAPHS * CCH) g_pool[i] = 0.f;
}

// ---------------- edge phase: msg = relu(x[src] + w*We + be); h[dst] += msg --
__global__ void edge_scatter_kernel(const float* __restrict__ x,
                                    const int*   __restrict__ ei,
                                    const float* __restrict__ ew,
                                    const float* __restrict__ We,
                                    const float* __restrict__ be,
                                    float* __restrict__ h) {
    __shared__ float sWe[CCH];
    __shared__ float sbe[CCH];
    int t = threadIdx.x;
    if (t < CCH) sWe[t] = We[t];
    else         sbe[t - CCH] = be[t - CCH];
    __syncthreads();

    int warp = t >> 5;
    int lane = t & 31;
    int e = blockIdx.x * 8 + warp;
    if (e >= N_EDGESC) return;

    int   s = ei[e];
    int   d = ei[N_EDGESC + e];
    float w = ew[e];
    int   c = lane * 4;

    float4 xv = *(const float4*)(x + (size_t)s * CCH + c);
    float4 m;
    m.x = fmaxf(fmaf(w, sWe[c + 0], xv.x) + sbe[c + 0], 0.f);
    m.y = fmaxf(fmaf(w, sWe[c + 1], xv.y) + sbe[c + 1], 0.f);
    m.z = fmaxf(fmaf(w, sWe[c + 2], xv.z) + sbe[c + 2], 0.f);
    m.w = fmaxf(fmaf(w, sWe[c + 3], xv.w) + sbe[c + 3], 0.f);

    float* p = h + (size_t)d * CCH + c;
    asm volatile("red.global.add.v4.f32 [%0], {%1, %2, %3, %4};"
                 :: "l"(p), "f"(m.x), "f"(m.y), "f"(m.z), "f"(m.w)
                 : "memory");
}

// ---------------- GEMM (FFMA2): out[m][n] = sum_k A'[m][k]*W[n][k] + bias[n] --
// A' = A                       (AFF=false)
// A' = relu(A*scale + shift)   (AFF=true; BN affine+ReLU folded into load)
// out = relu(out)              (RELU=true)
// STATS: accumulate column sum/sumsq of out into g_stats (pre-BN output)
// POOL : skip store; atomicMax out into g_pool[batch[m]] (values >= 0)
// BM=128, BN=128(full), BK=8, 256 threads, 8x8 thread tile, packed-pair math.
template <bool AFF, bool RELU, bool STATS, bool POOL>
__global__ void __launch_bounds__(256, 2)
gemm_f2_kernel(const float* __restrict__ A, const float* __restrict__ W,
               const float* __restrict__ bias, float* __restrict__ Cmat,
               const int* __restrict__ batch, int M) {
    __shared__ unsigned long long sAd[8][CCH];   // A dup pairs (a,a), [k][m], 8KB
    __shared__ float sB[8][CCH];                 // W, [k][n], 4KB
    __shared__ float sBias[CCH];
    __shared__ float sSc[CCH];
    __shared__ float sSh[CCH];

    int tid = threadIdx.x;
    if (tid < CCH) {
        sBias[tid] = bias[tid];
        if (AFF) {
            sSc[tid] = g_affine[tid];
            sSh[tid] = g_affine[CCH + tid];
        }
    }
    __syncthreads();

    int m0 = blockIdx.x * 128;
    int lr = tid >> 1;        // 0..127 (A row / W row for loads)
    int lq = tid & 1;         // which float4 of the 8-wide k slice
    int ty = tid >> 4;        // 0..15 -> m group
    int tx = tid & 15;        // 0..15 -> n group

    unsigned long long acc[8][4];
#pragma unroll
    for (int i = 0; i < 8; i++)
#pragma unroll
        for (int j = 0; j < 4; j++) acc[i][j] = 0ull;

    bool avalid = (m0 + lr) < M;
    const float* arow = A + (size_t)(m0 + lr) * CCH + lq * 4;
    const float* wrow = W + (size_t)lr * CCH + lq * 4;

    for (int k0 = 0; k0 < CCH; k0 += 8) {
        float4 av = avalid ? *(const float4*)(arow + k0)
                           : make_float4(0.f, 0.f, 0.f, 0.f);
        if (AFF) {
            int kb = k0 + lq * 4;
            av.x = fmaxf(fmaf(av.x, sSc[kb + 0], sSh[kb + 0]), 0.f);
            av.y = fmaxf(fmaf(av.y, sSc[kb + 1], sSh[kb + 1]), 0.f);
            av.z = fmaxf(fmaf(av.z, sSc[kb + 2], sSh[kb + 2]), 0.f);
            av.w = fmaxf(fmaf(av.w, sSc[kb + 3], sSh[kb + 3]), 0.f);
        }
        float4 wv = *(const float4*)(wrow + k0);
        int kl = lq * 4;
        sAd[kl + 0][lr] = pack2(av.x, av.x);
        sAd[kl + 1][lr] = pack2(av.y, av.y);
        sAd[kl + 2][lr] = pack2(av.z, av.z);
        sAd[kl + 3][lr] = pack2(av.w, av.w);
        sB[kl + 0][lr] = wv.x; sB[kl + 1][lr] = wv.y;
        sB[kl + 2][lr] = wv.z; sB[kl + 3][lr] = wv.w;
        __syncthreads();

#pragma unroll
        for (int kk = 0; kk < 8; kk++) {
            unsigned long long a2[8], b2[4];
            const ulonglong2* pa = (const ulonglong2*)&sAd[kk][ty * 8];
            ulonglong2 q0 = pa[0], q1 = pa[1], q2 = pa[2], q3 = pa[3];
            a2[0] = q0.x; a2[1] = q0.y; a2[2] = q1.x; a2[3] = q1.y;
            a2[4] = q2.x; a2[5] = q2.y; a2[6] = q3.x; a2[7] = q3.y;
            const ulonglong2* pb = (const ulonglong2*)&sB[kk][tx * 8];
            ulonglong2 r0 = pb[0], r1 = pb[1];
            b2[0] = r0.x; b2[1] = r0.y; b2[2] = r1.x; b2[3] = r1.y;
#pragma unroll
            for (int i = 0; i < 8; i++)
#pragma unroll
                for (int j = 0; j < 4; j++)
                    acc[i][j] = fma2(a2[i], b2[j], acc[i][j]);
        }
        __syncthreads();
    }

    // ---- epilogue ----
    float bj[8];
#pragma unroll
    for (int j = 0; j < 8; j++) bj[j] = sBias[tx * 8 + j];

    float sums[8], sqs[8];
    if (STATS) {
#pragma unroll
        for (int j = 0; j < 8; j++) { sums[j] = 0.f; sqs[j] = 0.f; }
    }

#pragma unroll
    for (int i = 0; i < 8; i++) {
        int m = m0 + ty * 8 + i;
        if (m >= M) break;
        float v[8];
#pragma unroll
        for (int jp = 0; jp < 4; jp++) {
            v[2 * jp]     = lo2(acc[i][jp]);
            v[2 * jp + 1] = hi2(acc[i][jp]);
        }
#pragma unroll
        for (int j = 0; j < 8; j++) {
            v[j] += bj[j];
            if (RELU) v[j] = fmaxf(v[j], 0.f);
        }
        if (!POOL) {
            float* crow = Cmat + (size_t)m * CCH + tx * 8;
            *(float4*)(crow)     = make_float4(v[0], v[1], v[2], v[3]);
            *(float4*)(crow + 4) = make_float4(v[4], v[5], v[6], v[7]);
        }
        if (STATS) {
#pragma unroll
            for (int j = 0; j < 8; j++) {
                sums[j] += v[j];
                sqs[j] = fmaf(v[j], v[j], sqs[j]);
            }
        }
        if (POOL) {
            int b = __ldg(batch + m);
            int* prow = (int*)&g_pool[(size_t)b * CCH + tx * 8];
#pragma unroll
            for (int j = 0; j < 8; j++)
                atomicMax(prow + j, __float_as_int(v[j]));
        }
    }

    if (STATS) {
        float* red = (float*)sAd;   // 16 x 128 floats = 8KB, reuse A buffer
        __syncthreads();
#pragma unroll
        for (int j = 0; j < 8; j++) red[ty * CCH + tx * 8 + j] = sums[j];
        __syncthreads();
        if (tid < CCH) {
            float s = 0.f;
#pragma unroll
            for (int r = 0; r < 16; r++) s += red[r * CCH + tid];
            atomicAdd(&g_stats[tid], s);
        }
        __syncthreads();
#pragma unroll
        for (int j = 0; j < 8; j++) red[ty * CCH + tx * 8 + j] = sqs[j];
        __syncthreads();
        if (tid < CCH) {
            float s = 0.f;
#pragma unroll
            for (int r = 0; r < 16; r++) s += red[r * CCH + tid];
            atomicAdd(&g_stats[CCH + tid], s);
        }
    }
}

// ---------------- BN finalize -------------------------------------------------
__global__ void bn_finalize_kernel(const float* __restrict__ g,
                                   const float* __restrict__ bt, float invN) {
    int c = threadIdx.x;                  // 128 threads
    float mu  = g_stats[c] * invN;
    float var = fmaf(-mu, mu, g_stats[CCH + c] * invN);
    float rs  = rsqrtf(var + 1e-5f);
    float sc  = g[c] * rs;
    g_affine[c]       = sc;
    g_affine[CCH + c] = fmaf(-mu, sc, bt[c]);
}

// ---------------- final linear [512,128] @ [5,128]^T + b -------------------
__global__ void final_linear_kernel(const float* __restrict__ lw,
                                    const float* __restrict__ lb,
                                    float* __restrict__ out) {
    int gph  = blockIdx.x;
    int o    = threadIdx.x >> 5;          // 5 warps
    int lane = threadIdx.x & 31;
    const float* p    = g_pool + (size_t)gph * CCH;
    const float* wrow = lw + (size_t)o * CCH;
    float s = 0.f;
    for (int c = lane; c < CCH; c += 32) s = fmaf(p[c], wrow[c], s);
#pragma unroll
    for (int d = 16; d; d >>= 1) s += __shfl_xor_sync(0xffffffffu, s, d);
    if (lane == 0) out[gph * N_OUTC + o] = s + lb[o];
}

// ---------------- launch ----------------------------------------------------
extern "C" void kernel_launch(void* const* d_in, const int* in_sizes, int n_in,
                              void* d_out, int out_size) {
    const float* x   = (const float*)d_in[0];
    const int*   ei  = (const int*)  d_in[1];
    const float* ew  = (const float*)d_in[2];
    const int*   bat = (const int*)  d_in[3];
    const float* P[18];
    for (int i = 0; i < 18; i++) P[i] = (const float*)d_in[4 + i];
    // P: We0 be0 W1_0 b1_0 g0 bt0 W2_0 b2_0 | We1 be1 W1_1 b1_1 g1 bt1 W2_1 b2_1 | lin_w lin_b
    float* out = (float*)d_out;

    float *ph, *ph1, *pxo;
    cudaGetSymbolAddress((void**)&ph,  g_h);
    cudaGetSymbolAddress((void**)&ph1, g_h1);
    cudaGetSymbolAddress((void**)&pxo, g_xo);

    const int NC4 = N_NODESC * CCH / 4;
    const int NBLK = (N_NODESC + 127) / 128;
    const float invN = 1.f / (float)N_NODESC;

    zero_pool_kernel<<<(N_GRAPHS * CCH + 255) / 256, 256>>>();

    const float* xin = x;
    for (int l = 0; l < 2; l++) {
        const float* We = P[l * 8 + 0];
        const float* be = P[l * 8 + 1];
        const float* W1 = P[l * 8 + 2];
        const float* b1 = P[l * 8 + 3];
        const float* gg = P[l * 8 + 4];
        const float* bt = P[l * 8 + 5];
        const float* W2 = P[l * 8 + 6];
        const float* b2 = P[l * 8 + 7];

        // h = x (the "(1+eps)*x" term, eps=0), then scatter-add messages
        copy4_kernel<<<(NC4 + 255) / 256, 256>>>((float4*)ph, (const float4*)xin, NC4);
        zero_stats_kernel<<<1, 256>>>();
        edge_scatter_kernel<<<N_EDGESC / 8, 256>>>(xin, ei, ew, We, be, ph);
        // h1 = h @ W1^T + b1, with fused BN stats
        gemm_f2_kernel<false, false, true, false><<<NBLK, 256>>>(ph, W1, b1, ph1, bat, N_NODESC);
        bn_finalize_kernel<<<1, 128>>>(gg, bt, invN);
        if (l == 0) {
            // x_out = relu( relu(BN(h1)) @ W2^T + b2 )
            gemm_f2_kernel<true, true, false, false><<<NBLK, 256>>>(ph1, W2, b2, pxo, bat, N_NODESC);
        } else {
            // last layer: fuse max-pool, skip output store
            gemm_f2_kernel<true, true, false, true><<<NBLK, 256>>>(ph1, W2, b2, pxo, bat, N_NODESC);
        }
        xin = pxo;
    }

    final_linear_kernel<<<N_GRAPHS, 160>>>(P[16], P[17], out);
}

// round 4
// speedup vs baseline: 1.2619x; 1.2619x over previous
#include <cuda_runtime.h>
#include <math.h>
#include <stdint.h>

#define N_NODESC 50000
#define N_EDGESC 800000
#define CCH      128
#define N_GRAPHS 512
#define N_OUTC   5
#define BKT_CAP  96

// ---------------- scratch (device globals: allocation-free) ----------------
__device__ __align__(128) float g_h [N_NODESC * CCH];   // h = x + aggr
__device__ __align__(128) float g_h1[N_NODESC * CCH];   // after first linear
__device__ __align__(128) float g_xo[N_NODESC * CCH];   // layer output
__device__ __align__(128) float g_stats [2 * CCH];      // col sums / sumsq
__device__ __align__(128) float g_affine[2 * CCH];      // BN scale / shift
__device__ __align__(128) float g_pool[N_GRAPHS * CCH]; // max pool
__device__ __align__(128) int   g_deg[N_NODESC];        // in-degree / cursor
__device__ __align__(128) int2  g_bucket[N_NODESC * BKT_CAP]; // (src, w-bits)

// ---------------- setup helpers ----------------
__global__ void zero_small_kernel() {
    int i = blockIdx.x * blockDim.x + threadIdx.x;
    if (i < 2 * CCH) g_stats[i] = 0.f;                   // reset not needed per layer here
    if (i < N_GRAPHS * CCH) g_pool[i] = 0.f;
    if (i < N_NODESC) g_deg[i] = 0;
}

__global__ void zero_stats_kernel() {
    g_stats[threadIdx.x] = 0.f;                          // 256 threads cover 2*CCH
}

// ---------------- bucket build: per-dst list of (src, weight) ---------------
__global__ void bucket_build_kernel(const int* __restrict__ ei,
                                    const float* __restrict__ ew) {
    int e = blockIdx.x * blockDim.x + threadIdx.x;
    if (e >= N_EDGESC) return;
    int s = ei[e];
    int d = ei[N_EDGESC + e];
    float w = ew[e];
    int p = atomicAdd(&g_deg[d], 1);
    g_bucket[(size_t)d * BKT_CAP + p] = make_int2(s, __float_as_int(w));
}

// ---------------- aggregation: h[n] = x[n] + sum_e relu(x[src]+w*We+be) -----
// one warp per node, lane handles 4 channels; one-ahead prefetch on the list
__global__ void __launch_bounds__(256)
node_agg_kernel(const float* __restrict__ x,
                const float* __restrict__ We,
                const float* __restrict__ be,
                float* __restrict__ h) {
    __shared__ float sWe[CCH];
    __shared__ float sbe[CCH];
    int t = threadIdx.x;
    if (t < CCH) sWe[t] = We[t];
    else         sbe[t - CCH] = be[t - CCH];
    __syncthreads();

    int warp = t >> 5;
    int lane = t & 31;
    int node = blockIdx.x * 8 + warp;
    if (node >= N_NODESC) return;

    int c = lane * 4;
    float w0 = sWe[c + 0], w1 = sWe[c + 1], w2 = sWe[c + 2], w3 = sWe[c + 3];
    float e0 = sbe[c + 0], e1 = sbe[c + 1], e2 = sbe[c + 2], e3 = sbe[c + 3];

    float4 acc = *(const float4*)(x + (size_t)node * CCH + c);  // self term

    int deg = __ldg(&g_deg[node]);
    const int2* bk = g_bucket + (size_t)node * BKT_CAP;

    int2 nxt = (deg > 0) ? __ldg(bk) : make_int2(0, 0);
    for (int j = 0; j < deg; j++) {
        int2 cur = nxt;
        if (j + 1 < deg) nxt = __ldg(bk + j + 1);
        float w = __int_as_float(cur.y);
        float4 xv = *(const float4*)(x + (size_t)cur.x * CCH + c);
        acc.x += fmaxf(fmaf(w, w0, xv.x) + e0, 0.f);
        acc.y += fmaxf(fmaf(w, w1, xv.y) + e1, 0.f);
        acc.z += fmaxf(fmaf(w, w2, xv.z) + e2, 0.f);
        acc.w += fmaxf(fmaf(w, w3, xv.w) + e3, 0.f);
    }
    *(float4*)(h + (size_t)node * CCH + c) = acc;
}

// ---------------- GEMM (R1 FFMA mainloop): out = A' @ W^T + bias ------------
// A' = A (AFF=false) or relu(A*scale+shift) (AFF=true); out=relu if RELU
// STATS: column sum/sumsq of out -> g_stats; POOL: atomicMax into g_pool, no store
template <bool AFF, bool RELU, bool STATS, bool POOL>
__global__ void gemm_nt_kernel(const float* __restrict__ A,
                               const float* __restrict__ W,
                               const float* __restrict__ bias,
                               float* __restrict__ Cmat,
                               const int* __restrict__ batch, int M) {
    __shared__ float sA[8][CCH];
    __shared__ float sB[8][CCH];
    __shared__ float sBias[CCH];
    __shared__ float sSc[CCH];
    __shared__ float sSh[CCH];

    int tid = threadIdx.x;
    if (tid < CCH) {
        sBias[tid] = bias[tid];
        if (AFF) {
            sSc[tid] = g_affine[tid];
            sSh[tid] = g_affine[CCH + tid];
        }
    }
    __syncthreads();

    int m0 = blockIdx.x * 128;
    int lr = tid >> 1;        // 0..127
    int lq = tid & 1;
    int ty = tid >> 4;        // 0..15
    int tx = tid & 15;        // 0..15

    float acc[8][8];
#pragma unroll
    for (int i = 0; i < 8; i++)
#pragma unroll
        for (int j = 0; j < 8; j++) acc[i][j] = 0.f;

    bool avalid = (m0 + lr) < M;
    const float* arow = A + (size_t)(m0 + lr) * CCH + lq * 4;
    const float* wrow = W + (size_t)lr * CCH + lq * 4;

    for (int k0 = 0; k0 < CCH; k0 += 8) {
        float4 av = avalid ? *(const float4*)(arow + k0)
                           : make_float4(0.f, 0.f, 0.f, 0.f);
        if (AFF) {
            int kb = k0 + lq * 4;
            av.x = fmaxf(fmaf(av.x, sSc[kb + 0], sSh[kb + 0]), 0.f);
            av.y = fmaxf(fmaf(av.y, sSc[kb + 1], sSh[kb + 1]), 0.f);
            av.z = fmaxf(fmaf(av.z, sSc[kb + 2], sSh[kb + 2]), 0.f);
            av.w = fmaxf(fmaf(av.w, sSc[kb + 3], sSh[kb + 3]), 0.f);
        }
        float4 wv = *(const float4*)(wrow + k0);
        int kl = lq * 4;
        sA[kl + 0][lr] = av.x; sA[kl + 1][lr] = av.y;
        sA[kl + 2][lr] = av.z; sA[kl + 3][lr] = av.w;
        sB[kl + 0][lr] = wv.x; sB[kl + 1][lr] = wv.y;
        sB[kl + 2][lr] = wv.z; sB[kl + 3][lr] = wv.w;
        __syncthreads();

#pragma unroll
        for (int kk = 0; kk < 8; kk++) {
            float a[8], b[8];
            *(float4*)&a[0] = *(const float4*)&sA[kk][ty * 8];
            *(float4*)&a[4] = *(const float4*)&sA[kk][ty * 8 + 4];
            *(float4*)&b[0] = *(const float4*)&sB[kk][tx * 8];
            *(float4*)&b[4] = *(const float4*)&sB[kk][tx * 8 + 4];
#pragma unroll
            for (int i = 0; i < 8; i++)
#pragma unroll
                for (int j = 0; j < 8; j++)
                    acc[i][j] = fmaf(a[i], b[j], acc[i][j]);
        }
        __syncthreads();
    }

    // ---- epilogue ----
    float bj[8];
#pragma unroll
    for (int j = 0; j < 8; j++) bj[j] = sBias[tx * 8 + j];

    float sums[8], sqs[8];
    if (STATS) {
#pragma unroll
        for (int j = 0; j < 8; j++) { sums[j] = 0.f; sqs[j] = 0.f; }
    }

#pragma unroll
    for (int i = 0; i < 8; i++) {
        int m = m0 + ty * 8 + i;
        if (m >= M) break;
        float v[8];
#pragma unroll
        for (int j = 0; j < 8; j++) {
            float tv = acc[i][j] + bj[j];
            if (RELU) tv = fmaxf(tv, 0.f);
            v[j] = tv;
        }
        if (!POOL) {
            float* crow = Cmat + (size_t)m * CCH + tx * 8;
            *(float4*)(crow)     = make_float4(v[0], v[1], v[2], v[3]);
            *(float4*)(crow + 4) = make_float4(v[4], v[5], v[6], v[7]);
        }
        if (STATS) {
#pragma unroll
            for (int j = 0; j < 8; j++) {
                sums[j] += v[j];
                sqs[j] = fmaf(v[j], v[j], sqs[j]);
            }
        }
        if (POOL) {
            int b = __ldg(batch + m);
            int* prow = (int*)&g_pool[(size_t)b * CCH + tx * 8];
#pragma unroll
            for (int j = 0; j < 8; j++)
                atomicMax(prow + j, __float_as_int(v[j]));
        }
    }

    if (STATS) {
        float* red = (float*)sA;   // 16 x 128 floats = 8KB (sA+sB reuse)
        __syncthreads();
#pragma unroll
        for (int j = 0; j < 8; j++) red[ty * CCH + tx * 8 + j] = sums[j];
        __syncthreads();
        if (tid < CCH) {
            float s = 0.f;
#pragma unroll
            for (int r = 0; r < 16; r++) s += red[r * CCH + tid];
            atomicAdd(&g_stats[tid], s);
        }
        __syncthreads();
#pragma unroll
        for (int j = 0; j < 8; j++) red[ty * CCH + tx * 8 + j] = sqs[j];
        __syncthreads();
        if (tid < CCH) {
            float s = 0.f;
#pragma unroll
            for (int r = 0; r < 16; r++) s += red[r * CCH + tid];
            atomicAdd(&g_stats[CCH + tid], s);
        }
    }
}

// ---------------- BN finalize ------------------------------------------------
__global__ void bn_finalize_kernel(const float* __restrict__ g,
                                   const float* __restrict__ bt, float invN) {
    int c = threadIdx.x;                  // 128 threads
    float mu  = g_stats[c] * invN;
    float var = fmaf(-mu, mu, g_stats[CCH + c] * invN);
    float rs  = rsqrtf(var + 1e-5f);
    float sc  = g[c] * rs;
    g_affine[c]       = sc;
    g_affine[CCH + c] = fmaf(-mu, sc, bt[c]);
}

// ---------------- final linear [512,128] @ [5,128]^T + b --------------------
__global__ void final_linear_kernel(const float* __restrict__ lw,
                                    const float* __restrict__ lb,
                                    float* __restrict__ out) {
    int gph  = blockIdx.x;
    int o    = threadIdx.x >> 5;          // 5 warps
    int lane = threadIdx.x & 31;
    const float* p    = g_pool + (size_t)gph * CCH;
    const float* wrow = lw + (size_t)o * CCH;
    float s = 0.f;
    for (int c = lane; c < CCH; c += 32) s = fmaf(p[c], wrow[c], s);
#pragma unroll
    for (int d = 16; d; d >>= 1) s += __shfl_xor_sync(0xffffffffu, s, d);
    if (lane == 0) out[gph * N_OUTC + o] = s + lb[o];
}

// ---------------- launch -----------------------------------------------------
extern "C" void kernel_launch(void* const* d_in, const int* in_sizes, int n_in,
                              void* d_out, int out_size) {
    const float* x   = (const float*)d_in[0];
    const int*   ei  = (const int*)  d_in[1];
    const float* ew  = (const float*)d_in[2];
    const int*   bat = (const int*)  d_in[3];
    const float* P[18];
    for (int i = 0; i < 18; i++) P[i] = (const float*)d_in[4 + i];
    // P: We0 be0 W1_0 b1_0 g0 bt0 W2_0 b2_0 | We1 be1 W1_1 b1_1 g1 bt1 W2_1 b2_1 | lin_w lin_b
    float* out = (float*)d_out;

    float *ph, *ph1, *pxo;
    cudaGetSymbolAddress((void**)&ph,  g_h);
    cudaGetSymbolAddress((void**)&ph1, g_h1);
    cudaGetSymbolAddress((void**)&pxo, g_xo);

    const int NBLK = (N_NODESC + 127) / 128;
    const int AGG_BLK = (N_NODESC + 7) / 8;
    const float invN = 1.f / (float)N_NODESC;

    // reset pool + degree counters, build per-dst buckets (layer-invariant)
    zero_small_kernel<<<(N_GRAPHS * CCH + 255) / 256, 256>>>();
    bucket_build_kernel<<<(N_EDGESC + 255) / 256, 256>>>(ei, ew);

    const float* xin = x;
    for (int l = 0; l < 2; l++) {
        const float* We = P[l * 8 + 0];
        const float* be = P[l * 8 + 1];
        const float* W1 = P[l * 8 + 2];
        const float* b1 = P[l * 8 + 3];
        const float* gg = P[l * 8 + 4];
        const float* bt = P[l * 8 + 5];
        const float* W2 = P[l * 8 + 6];
        const float* b2 = P[l * 8 + 7];

        zero_stats_kernel<<<1, 256>>>();
        // h = x + sum_in relu(x[src] + w*We + be)   (self term folded in)
        node_agg_kernel<<<AGG_BLK, 256>>>(xin, We, be, ph);
        // h1 = h @ W1^T + b1, fused BN stats
        gemm_nt_kernel<false, false, true, false><<<NBLK, 256>>>(ph, W1, b1, ph1, bat, N_NODESC);
        bn_finalize_kernel<<<1, 128>>>(gg, bt, invN);
        if (l == 0) {
            gemm_nt_kernel<true, true, false, false><<<NBLK, 256>>>(ph1, W2, b2, pxo, bat, N_NODESC);
        } else {
            // last layer: fused max-pool, no output store
            gemm_nt_kernel<true, true, false, true><<<NBLK, 256>>>(ph1, W2, b2, pxo, bat, N_NODESC);
        }
        xin = pxo;
    }

    final_linear_kernel<<<N_GRAPHS, 160>>>(P[16], P[17], out);
}

// round 6
// speedup vs baseline: 1.6799x; 1.3312x over previous
#include <cuda_runtime.h>
#include <cuda_bf16.h>
#include <math.h>
#include <stdint.h>

#define N_NODESC 50000
#define N_EDGESC 800000
#define CCH      128
#define N_GRAPHS 512
#define N_OUTC   5
#define BKT_CAP  96
#define PAD      136   // bf16 elements per SMEM row (conflict-free ldmatrix)

// ---------------- scratch (device globals: allocation-free) ----------------
__device__ __align__(128) float g_h [N_NODESC * CCH];   // h = x + aggr
__device__ __align__(128) float g_h1[N_NODESC * CCH];   // after first linear
__device__ __align__(128) float g_xo[N_NODESC * CCH];   // layer output
__device__ __align__(128) float g_stats [2 * CCH];      // col sums / sumsq
__device__ __align__(128) float g_affine[2 * CCH];      // BN scale / shift
__device__ __align__(128) float g_pool[N_GRAPHS * CCH]; // max pool
__device__ __align__(128) int   g_deg[N_NODESC];        // in-degree / cursor
__device__ __align__(128) int2  g_bucket[N_NODESC * BKT_CAP]; // (src, w-bits)

// ---------------- PTX helpers ------------------------------------------------
__device__ __forceinline__ uint32_t smem_u32(const void* p) {
    uint32_t a;
    asm("{ .reg .u64 t; cvta.to.shared.u64 t, %1; cvt.u32.u64 %0, t; }"
        : "=r"(a) : "l"(p));
    return a;
}
__device__ __forceinline__ void ldmx4(uint32_t* r, uint32_t a) {
    asm volatile("ldmatrix.sync.aligned.m8n8.x4.shared.b16 {%0,%1,%2,%3}, [%4];"
                 : "=r"(r[0]), "=r"(r[1]), "=r"(r[2]), "=r"(r[3]) : "r"(a));
}
__device__ __forceinline__ void ldmx2(uint32_t* r, uint32_t a) {
    asm volatile("ldmatrix.sync.aligned.m8n8.x2.shared.b16 {%0,%1}, [%2];"
                 : "=r"(r[0]), "=r"(r[1]) : "r"(a));
}
__device__ __forceinline__ void mma16816(float* d, const uint32_t* a, const uint32_t* b) {
    asm volatile("mma.sync.aligned.m16n8k16.row.col.f32.bf16.bf16.f32 "
                 "{%0,%1,%2,%3}, {%4,%5,%6,%7}, {%8,%9}, {%0,%1,%2,%3};"
                 : "+f"(d[0]), "+f"(d[1]), "+f"(d[2]), "+f"(d[3])
                 : "r"(a[0]), "r"(a[1]), "r"(a[2]), "r"(a[3]), "r"(b[0]), "r"(b[1]));
}
__device__ __forceinline__ uint32_t pk_hi(float x, float y,
                                          uint32_t& lo_out) {
    __nv_bfloat16 hx = __float2bfloat16(x);
    __nv_bfloat16 hy = __float2bfloat16(y);
    __nv_bfloat16 lx = __float2bfloat16(x - __bfloat162float(hx));
    __nv_bfloat16 ly = __float2bfloat16(y - __bfloat162float(hy));
    lo_out = (uint32_t)__bfloat16_as_ushort(lx) |
             ((uint32_t)__bfloat16_as_ushort(ly) << 16);
    return (uint32_t)__bfloat16_as_ushort(hx) |
           ((uint32_t)__bfloat16_as_ushort(hy) << 16);
}

// ---------------- setup helpers ----------------
__global__ void zero_small_kernel() {
    int i = blockIdx.x * blockDim.x + threadIdx.x;
    if (i < N_GRAPHS * CCH) g_pool[i] = 0.f;
    if (i < N_NODESC) g_deg[i] = 0;
}
__global__ void zero_stats_kernel() {
    g_stats[threadIdx.x] = 0.f;          // 256 threads cover 2*CCH
}

// ---------------- bucket build: per-dst list of (src, weight) ---------------
__global__ void bucket_build_kernel(const int* __restrict__ ei,
                                    const float* __restrict__ ew) {
    int e = blockIdx.x * blockDim.x + threadIdx.x;
    if (e >= N_EDGESC) return;
    int s = ei[e];
    int d = ei[N_EDGESC + e];
    float w = ew[e];
    int p = atomicAdd(&g_deg[d], 1);
    g_bucket[(size_t)d * BKT_CAP + p] = make_int2(s, __float_as_int(w));
}

// ---------------- aggregation: h[n] = x[n] + sum_e relu(x[src]+w*We+be) -----
__global__ void __launch_bounds__(256)
node_agg_kernel(const float* __restrict__ x,
                const float* __restrict__ We,
                const float* __restrict__ be,
                float* __restrict__ h) {
    __shared__ float sWe[CCH];
    __shared__ float sbe[CCH];
    int t = threadIdx.x;
    if (t < CCH) sWe[t] = We[t];
    else         sbe[t - CCH] = be[t - CCH];
    __syncthreads();

    int warp = t >> 5;
    int lane = t & 31;
    int node = blockIdx.x * 8 + warp;
    if (node >= N_NODESC) return;

    int c = lane * 4;
    float w0 = sWe[c + 0], w1 = sWe[c + 1], w2 = sWe[c + 2], w3 = sWe[c + 3];
    float e0 = sbe[c + 0], e1 = sbe[c + 1], e2 = sbe[c + 2], e3 = sbe[c + 3];

    float4 acc = *(const float4*)(x + (size_t)node * CCH + c);  // self term

    int deg = __ldg(&g_deg[node]);
    const int2* bk = g_bucket + (size_t)node * BKT_CAP;

    int2 nxt = (deg > 0) ? __ldg(bk) : make_int2(0, 0);
    for (int j = 0; j < deg; j++) {
        int2 cur = nxt;
        if (j + 1 < deg) nxt = __ldg(bk + j + 1);
        float w = __int_as_float(cur.y);
        float4 xv = *(const float4*)(x + (size_t)cur.x * CCH + c);
        acc.x += fmaxf(fmaf(w, w0, xv.x) + e0, 0.f);
        acc.y += fmaxf(fmaf(w, w1, xv.y) + e1, 0.f);
        acc.z += fmaxf(fmaf(w, w2, xv.z) + e2, 0.f);
        acc.w += fmaxf(fmaf(w, w3, xv.w) + e3, 0.f);
    }
    *(float4*)(h + (size_t)node * CCH + c) = acc;
}

// ---------------- HMMA GEMM: out = A' @ W^T + bias --------------------------
// bf16 3-pass split (AhBh + AhBl + AlBh) for fp32-class accuracy.
// A' = A (AFF=false) or relu(A*scale+shift) (AFF=true); out=relu if RELU.
// STATS: column sum/sumsq -> g_stats. POOL: atomicMax -> g_pool, no store.
// CTA: 128 rows x 128 cols, K=128 resident. 8 warps (2 m x 4 n), warp 64x32.
static constexpr int SMEM_GEMM =
    4 * 128 * PAD * 2 + (3 * 128 + 256) * 4;   // 139264 + 2560 = 141824

template <bool AFF, bool RELU, bool STATS, bool POOL>
__global__ void __launch_bounds__(256, 1)
gemm_mma_kernel(const float* __restrict__ A, const float* __restrict__ W,
                const float* __restrict__ bias, float* __restrict__ Cmat,
                const int* __restrict__ batch, int M) {
    extern __shared__ char smraw[];
    __nv_bfloat16* sAh = (__nv_bfloat16*)smraw;
    __nv_bfloat16* sAl = sAh + 128 * PAD;
    __nv_bfloat16* sBh = sAl + 128 * PAD;
    __nv_bfloat16* sBl = sBh + 128 * PAD;
    float* sBias  = (float*)(sBl + 128 * PAD);   // 128
    float* sSc    = sBias + 128;
    float* sSh    = sSc + 128;
    float* sStats = sSh + 128;                   // 256

    int tid  = threadIdx.x;
    int wid  = tid >> 5;
    int lane = tid & 31;
    int wm   = wid & 1;        // 0..1 : 64-row half
    int wn   = wid >> 1;       // 0..3 : 32-col quarter
    int m0   = blockIdx.x * 128;

    if (tid < CCH) {
        sBias[tid] = bias[tid];
        if (AFF) {
            sSc[tid] = g_affine[tid];
            sSh[tid] = g_affine[CCH + tid];
        }
    }
    if (STATS && tid < 256) sStats[tid] = 0.f;
    __syncthreads();   // sSc/sSh/sBias/sStats must be visible before use

    // ---- load + split A and W into bf16 hi/lo SMEM tiles ----
    {
        int r  = tid >> 1;            // 0..127
        int ch = (tid & 1) * 64;      // col half
        bool valid = (m0 + r) < M;
        const float* arow = A + (size_t)(m0 + r) * CCH + ch;
        const float* wrow = W + (size_t)r * CCH + ch;
        uint32_t abase = (uint32_t)(r * PAD + ch);
#pragma unroll
        for (int q = 0; q < 64; q += 4) {
            float4 v = valid ? *(const float4*)(arow + q)
                             : make_float4(0.f, 0.f, 0.f, 0.f);
            if (AFF) {
                int k = ch + q;
                v.x = fmaxf(fmaf(v.x, sSc[k + 0], sSh[k + 0]), 0.f);
                v.y = fmaxf(fmaf(v.y, sSc[k + 1], sSh[k + 1]), 0.f);
                v.z = fmaxf(fmaf(v.z, sSc[k + 2], sSh[k + 2]), 0.f);
                v.w = fmaxf(fmaf(v.w, sSc[k + 3], sSh[k + 3]), 0.f);
            }
            uint2 hi, lo;
            hi.x = pk_hi(v.x, v.y, lo.x);
            hi.y = pk_hi(v.z, v.w, lo.y);
            *(uint2*)(sAh + abase + q) = hi;
            *(uint2*)(sAl + abase + q) = lo;

            float4 wv = *(const float4*)(wrow + q);
            hi.x = pk_hi(wv.x, wv.y, lo.x);
            hi.y = pk_hi(wv.z, wv.w, lo.y);
            *(uint2*)(sBh + abase + q) = hi;
            *(uint2*)(sBl + abase + q) = lo;
        }
    }
    __syncthreads();

    // ---- ldmatrix per-lane address offsets (in elements) ----
    int a_row = (lane & 7) + ((lane >> 3) & 1) * 8;
    int a_k   = (lane >> 4) * 8;
    int b_row = lane & 7;
    int b_k   = ((lane >> 3) & 1) * 8;

    uint32_t uAh = smem_u32(sAh), uAl = smem_u32(sAl);
    uint32_t uBh = smem_u32(sBh), uBl = smem_u32(sBl);

    float acc[4][4][4];
#pragma unroll
    for (int i = 0; i < 4; i++)
#pragma unroll
        for (int j = 0; j < 4; j++)
#pragma unroll
            for (int q = 0; q < 4; q++) acc[i][j][q] = 0.f;

    for (int k0 = 0; k0 < CCH; k0 += 16) {
        uint32_t ah[4][4], al[4][4], bh[4][2], bl[4][2];
#pragma unroll
        for (int mt = 0; mt < 4; mt++) {
            uint32_t off = (uint32_t)(((wm * 64 + mt * 16 + a_row) * PAD + k0 + a_k) * 2);
            ldmx4(ah[mt], uAh + off);
            ldmx4(al[mt], uAl + off);
        }
#pragma unroll
        for (int nt = 0; nt < 4; nt++) {
            uint32_t off = (uint32_t)(((wn * 32 + nt * 8 + b_row) * PAD + k0 + b_k) * 2);
            ldmx2(bh[nt], uBh + off);
            ldmx2(bl[nt], uBl + off);
        }
#pragma unroll
        for (int mt = 0; mt < 4; mt++)
#pragma unroll
            for (int nt = 0; nt < 4; nt++) {
                mma16816(acc[mt][nt], ah[mt], bh[nt]);
                mma16816(acc[mt][nt], ah[mt], bl[nt]);
                mma16816(acc[mt][nt], al[mt], bh[nt]);
            }
    }

    // ---- epilogue ----
    float sums[4][2], sqs[4][2];
    if (STATS) {
#pragma unroll
        for (int nt = 0; nt < 4; nt++) {
            sums[nt][0] = sums[nt][1] = 0.f;
            sqs[nt][0] = sqs[nt][1] = 0.f;
        }
    }

#pragma unroll
    for (int nt = 0; nt < 4; nt++) {
        int col = wn * 32 + nt * 8 + (lane & 3) * 2;
        float b0 = sBias[col], b1 = sBias[col + 1];
#pragma unroll
        for (int mt = 0; mt < 4; mt++) {
#pragma unroll
            for (int hf = 0; hf < 2; hf++) {
                int m = m0 + wm * 64 + mt * 16 + (lane >> 2) + hf * 8;
                if (m < M) {
                    float v0 = acc[mt][nt][hf * 2 + 0] + b0;
                    float v1 = acc[mt][nt][hf * 2 + 1] + b1;
                    if (RELU) { v0 = fmaxf(v0, 0.f); v1 = fmaxf(v1, 0.f); }
                    if (!POOL)
                        *(float2*)(Cmat + (size_t)m * CCH + col) = make_float2(v0, v1);
                    if (STATS) {
                        sums[nt][0] += v0; sums[nt][1] += v1;
                        sqs[nt][0] = fmaf(v0, v0, sqs[nt][0]);
                        sqs[nt][1] = fmaf(v1, v1, sqs[nt][1]);
                    }
                    if (POOL) {
                        int b = __ldg(batch + m);
                        int* prow = (int*)&g_pool[(size_t)b * CCH + col];
                        atomicMax(prow,     __float_as_int(v0));
                        atomicMax(prow + 1, __float_as_int(v1));
                    }
                }
            }
        }
    }

    if (STATS) {
#pragma unroll
        for (int nt = 0; nt < 4; nt++) {
            int col = wn * 32 + nt * 8 + (lane & 3) * 2;
            atomicAdd(&sStats[col],           sums[nt][0]);
            atomicAdd(&sStats[col + 1],       sums[nt][1]);
            atomicAdd(&sStats[128 + col],     sqs[nt][0]);
            atomicAdd(&sStats[128 + col + 1], sqs[nt][1]);
        }
        __syncthreads();
        if (tid < 256) atomicAdd(&g_stats[tid], sStats[tid]);
    }
}

// ---------------- BN finalize ------------------------------------------------
__global__ void bn_finalize_kernel(const float* __restrict__ g,
                                   const float* __restrict__ bt, float invN) {
    int c = threadIdx.x;                  // 128 threads
    float mu  = g_stats[c] * invN;
    float var = fmaf(-mu, mu, g_stats[CCH + c] * invN);
    float rs  = rsqrtf(var + 1e-5f);
    float sc  = g[c] * rs;
    g_affine[c]       = sc;
    g_affine[CCH + c] = fmaf(-mu, sc, bt[c]);
}

// ---------------- final linear [512,128] @ [5,128]^T + b --------------------
__global__ void final_linear_kernel(const float* __restrict__ lw,
                                    const float* __restrict__ lb,
                                    float* __restrict__ out) {
    int gph  = blockIdx.x;
    int o    = threadIdx.x >> 5;          // 5 warps
    int lane = threadIdx.x & 31;
    const float* p    = g_pool + (size_t)gph * CCH;
    const float* wrow = lw + (size_t)o * CCH;
    float s = 0.f;
    for (int c = lane; c < CCH; c += 32) s = fmaf(p[c], wrow[c], s);
#pragma unroll
    for (int d = 16; d; d >>= 1) s += __shfl_xor_sync(0xffffffffu, s, d);
    if (lane == 0) out[gph * N_OUTC + o] = s + lb[o];
}

// ---------------- launch -----------------------------------------------------
extern "C" void kernel_launch(void* const* d_in, const int* in_sizes, int n_in,
                              void* d_out, int out_size) {
    const float* x   = (const float*)d_in[0];
    const int*   ei  = (const int*)  d_in[1];
    const float* ew  = (const float*)d_in[2];
    const int*   bat = (const int*)  d_in[3];
    const float* P[18];
    for (int i = 0; i < 18; i++) P[i] = (const float*)d_in[4 + i];
    // P: We0 be0 W1_0 b1_0 g0 bt0 W2_0 b2_0 | We1 be1 W1_1 b1_1 g1 bt1 W2_1 b2_1 | lin_w lin_b
    float* out = (float*)d_out;

    float *ph, *ph1, *pxo;
    cudaGetSymbolAddress((void**)&ph,  g_h);
    cudaGetSymbolAddress((void**)&ph1, g_h1);
    cudaGetSymbolAddress((void**)&pxo, g_xo);

    cudaFuncSetAttribute(gemm_mma_kernel<false, false, true, false>,
                         cudaFuncAttributeMaxDynamicSharedMemorySize, SMEM_GEMM);
    cudaFuncSetAttribute(gemm_mma_kernel<true, true, false, false>,
                         cudaFuncAttributeMaxDynamicSharedMemorySize, SMEM_GEMM);
    cudaFuncSetAttribute(gemm_mma_kernel<true, true, false, true>,
                         cudaFuncAttributeMaxDynamicSharedMemorySize, SMEM_GEMM);

    const int NBLK = (N_NODESC + 127) / 128;
    const int AGG_BLK = (N_NODESC + 7) / 8;
    const float invN = 1.f / (float)N_NODESC;

    zero_small_kernel<<<(N_GRAPHS * CCH + 255) / 256, 256>>>();
    bucket_build_kernel<<<(N_EDGESC + 255) / 256, 256>>>(ei, ew);

    const float* xin = x;
    for (int l = 0; l < 2; l++) {
        const float* We = P[l * 8 + 0];
        const float* be = P[l * 8 + 1];
        const float* W1 = P[l * 8 + 2];
        const float* b1 = P[l * 8 + 3];
        const float* gg = P[l * 8 + 4];
        const float* bt = P[l * 8 + 5];
        const float* W2 = P[l * 8 + 6];
        const float* b2 = P[l * 8 + 7];

        zero_stats_kernel<<<1, 256>>>();
        node_agg_kernel<<<AGG_BLK, 256>>>(xin, We, be, ph);
        gemm_mma_kernel<false, false, true, false>
            <<<NBLK, 256, SMEM_GEMM>>>(ph, W1, b1, ph1, bat, N_NODESC);
        bn_finalize_kernel<<<1, 128>>>(gg, bt, invN);
        if (l == 0) {
            gemm_mma_kernel<true, true, false, false>
                <<<NBLK, 256, SMEM_GEMM>>>(ph1, W2, b2, pxo, bat, N_NODESC);
        } else {
            gemm_mma_kernel<true, true, false, true>
                <<<NBLK, 256, SMEM_GEMM>>>(ph1, W2, b2, pxo, bat, N_NODESC);
        }
        xin = pxo;
    }

    final_linear_kernel<<<N_GRAPHS, 160>>>(P[16], P[17], out);
}